// round 10
// baseline (speedup 1.0000x reference)
#include <cuda_runtime.h>
#include <math.h>

#define BB 16
#define NN 8400
#define GG 128
#define NCL 5
#define BN (BB*NN)      // 134400
#define BGT (BB*GG)     // 2048
#define NQ4 (NN/4)      // 2100 float4s per row
#define MAXTK 18
#define EPSF 1e-9f
#define HPI_F 1.57079632679489662f
#define PI_F  3.14159265358979323f
#define IPI_F 0.318309886183790672f

typedef unsigned long long u64;

struct GTC {
    float gx, gy, ct, st;
    float w15, h15, inv_s2, inv_sc2;
    float factor, gth;
    int budget, fbk, flags, lbl;
    float pad0, pad1;
};

__device__ GTC           d_gt[BGT];
__device__ float         d_am[(size_t)BGT * NN];  // [b][g][n]
__device__ u64           d_best[BN];              // (val<<32)|(127-g)
__device__ int           d_norm[BN];
__device__ unsigned char d_pos[BN];
__device__ int           d_cnt[BGT];              // nonzero in-center flag

// ---------------------------------------------------------------------------
__global__ __launch_bounds__(256) void prep_gt(const int* __restrict__ gl,
                                               const float* __restrict__ gb,
                                               const float* __restrict__ mg) {
    int bg = blockIdx.x * 256 + threadIdx.x;
    if (bg >= BGT) return;
    const float* g = gb + (size_t)bg * 5;
    float gx = g[0], gy = g[1], w = g[2], h = g[3], th = g[4];
    float wc = fmaxf(w, EPSF), hc = fmaxf(h, EPSF);
    float area = wc * hc;
    float ar = fmaxf(wc / hc, hc / wc);
    float sev = fminf(fmaxf((0.01f - area) / (0.01f + EPSF), 0.f), 1.f);
    int te = (int)ceilf(sev * 4.f);
    int el = (ar >= 4.f) ? 1 : 0;
    GTC q;
    q.gx = gx; q.gy = gy;
    q.ct = cosf(-th); q.st = sinf(-th);
    q.w15 = w * 1.5f; q.h15 = h * 1.5f;
    float sc = sqrtf(w * h);
    float is = 1.f / (sc + 1e-6f);         q.inv_s2  = is * is;
    float isc = 1.f / (sc * 1.5f + 1e-6f); q.inv_sc2 = isc * isc;
    float strength = fminf(fmaxf((ar - 4.f) / (4.f + EPSF), 0.f), 1.f);
    q.factor = (1.f + sev * (4.f / 13.f)) * (1.f + 0.25f * strength);
    q.gth = th;
    q.budget = 13 + te + el;
    q.fbk = te + el + 3;
    int fl = (mg[bg] > 0.f) ? 1 : 0;
    if ((area < 0.01f) || (ar >= 4.f)) fl |= 2;
    q.flags = fl;
    q.lbl = gl[bg];
    q.pad0 = 0.f; q.pad1 = 0.f;
    d_gt[bg] = q;
    d_cnt[bg] = 0;
}

// ---------------------------------------------------------------------------
// A (R8): block = (512-anchor tile, b), 512 threads, 1 anchor/thread.
// ---------------------------------------------------------------------------
__global__ __launch_bounds__(512) void pair_kernel(const float2* __restrict__ anch,
                                                   const float* __restrict__ ps,
                                                   const float* __restrict__ pbx) {
    int b   = blockIdx.y;
    int tid = threadIdx.x;
    int n   = blockIdx.x * 512 + tid;

    __shared__ GTC           s_gt[GG];     // 8 KB
    __shared__ unsigned char s_any[GG];

    {
        const float4* src = (const float4*)(d_gt + b * GG);
        float4*       dst = (float4*)s_gt;
        dst[tid] = src[tid];
        if (tid < GG) s_any[tid] = 0;
    }
    __syncthreads();

    bool valid = (n < NN);
    float ax = 0.f, ay = 0.f, px = 0.f, py = 0.f, pt = 0.f;
    float l0 = 0.f, l1 = 0.f, l2 = 0.f, l3 = 0.f, l4 = 0.f;
    if (valid) {
        float2 a = anch[n];
        ax = a.x; ay = a.y;
        size_t base = (size_t)(b * NN + n) * 5;
        px = pbx[base]; py = pbx[base + 1]; pt = pbx[base + 4];
#define LC(d, i) { float sg = 1.f/(1.f+__expf(-ps[base+(i)])); \
                   sg = fminf(fmaxf(sg, EPSF), 1.f); d = 0.5f*__logf(sg+EPSF); }
        LC(l0,0) LC(l1,1) LC(l2,2) LC(l3,3) LC(l4,4)
#undef LC
    }

    float bv = 0.f;
    int   bgi = 0;
    float* amp = d_am + (size_t)b * GG * NN + n;

    for (int g = 0; g < GG; g++) {
        GTC q = s_gt[g];
        if (!(q.flags & 1)) continue;
        float dxa = ax - q.gx, dya = ay - q.gy;
        float lx = dxa * q.ct - dya * q.st;
        float ly = dxa * q.st + dya * q.ct;
        bool in = valid && (fabsf(lx) < q.w15) && (fabsf(ly) < q.h15);
        float vv = 0.f;
        if (__ballot_sync(0xffffffffu, in)) {
            if ((tid & 31) == 0) s_any[g] = 1;
            if (in) {
                float dxp = px - q.gx, dyp = py - q.gy;
                float t = (dxp * dxp + dyp * dyp) * q.inv_s2;
                float x = __expf(-t) + EPSF;
                float x2 = x * x; float x6 = x2 * x2 * x2;
                float wv = (pt - q.gth) + HPI_F;
                wv -= PI_F * floorf(wv * IPI_F);
                float wr = fabsf(wv - HPI_F);
                float c = (dxa * dxa + dya * dya) * q.inv_sc2;
                int lb = q.lbl;
                float lcl = lb == 0 ? l0 : (lb == 1 ? l1 : (lb == 2 ? l2 : (lb == 3 ? l3 : l4)));
                vv = fmaxf(q.factor * x6 * __expf(lcl - 1.5f * wr - c), 0.f);
            }
        }
        if (valid) amp[(size_t)g * NN] = vv;
        if (vv > bv) { bv = vv; bgi = g; }
    }
    __syncthreads();
    if (tid < GG && s_any[tid]) atomicOr(&d_cnt[b * GG + tid], 1);
    if (valid) {
        int idx = b * NN + n;
        d_best[idx] = ((u64)__float_as_uint(bv) << 32) | (unsigned)(127 - bgi);
        d_norm[idx] = 0;
        d_pos[idx]  = 0;
    }
}

// ---------------------------------------------------------------------------
// B: block per (b,g). Single gmem streaming pass with per-column TOP-2 in
// registers (thread tid owns column tid: i = tid + k*256, n = 4i+j).
// Extraction: first hit on a column -> precomputed 2nd best (no rescan);
// repeat hits -> warp-parallel L2 rescan (rare). No 33.6KB smem row.
// ---------------------------------------------------------------------------
__global__ __launch_bounds__(256) void topk_kernel(const float2* __restrict__ anch,
                                                   const float* __restrict__ ps,
                                                   const float* __restrict__ pbx) {
    int bg = blockIdx.x;
    int b  = bg >> 7;
    int g  = bg & 127;
    GTC q = d_gt[bg];
    if (!(q.flags & 1)) return;

    int tid = threadIdx.x, lane = tid & 31, wid = tid >> 5;

    __shared__ u64           s_k1[256], s_k2[256];
    __shared__ u64           s_rm[256];
    __shared__ u64           s_red[8];
    __shared__ unsigned char s_ecnt[256];
    __shared__ unsigned      s_chosen[8];
    __shared__ int           s_pn[8];
    __shared__ float         s_pv[8];
    __shared__ int           s_np;

    const float*  amrow = d_am + (size_t)bg * NN;
    const float4* am4   = (const float4*)amrow;
    bool fb = (d_cnt[bg] == 0) && (q.flags & 2);

    if (tid == 0) s_np = 0;
    s_rm[tid] = 0;
    s_ecnt[tid] = 0;

    // -------- tiny/elongated fallback (rare): smem patch list --------
    if (fb) {
        __syncthreads();
        for (int r = 0; r < 8; r++) {
            u64 key = 0xFFFFFFFFFFFFFFFFull;
            for (int n = tid; n < NN; n += 256) {
                bool skip = false;
                for (int qq = 0; qq < r; qq++)
                    if (s_chosen[qq] == (unsigned)n) skip = true;
                if (!skip) {
                    float2 a = anch[n];
                    float dx = a.x - q.gx, dy = a.y - q.gy;
                    float d2 = dx * dx + dy * dy;
                    u64 k = ((u64)__float_as_uint(d2) << 32) | (unsigned)n;
                    if (k < key) key = k;
                }
            }
#pragma unroll
            for (int o = 16; o; o >>= 1) {
                u64 t = __shfl_xor_sync(0xffffffffu, key, o);
                if (t < key) key = t;
            }
            if (lane == 0) s_red[wid] = key;
            __syncthreads();
            if (wid == 0) {
                u64 v = (lane < 8) ? s_red[lane] : 0xFFFFFFFFFFFFFFFFull;
#pragma unroll
                for (int o = 4; o; o >>= 1) {
                    u64 t = __shfl_xor_sync(0xffffffffu, v, o);
                    if (t < v) v = t;
                }
                if (lane == 0) s_chosen[r] = (unsigned)(v & 0xffffffffu);
            }
            __syncthreads();
            unsigned nw = s_chosen[r];
            if (r < q.fbk && (int)(nw & 255u) == tid) {
                int n = (int)nw;
                float2 a = anch[n];
                float dxa = a.x - q.gx, dya = a.y - q.gy;
                size_t base = (size_t)(b * NN + n) * 5;
                float dxp = pbx[base] - q.gx, dyp = pbx[base + 1] - q.gy;
                float t = (dxp * dxp + dyp * dyp) * q.inv_s2;
                float x = __expf(-t) + EPSF;
                float x2 = x * x; float x6 = x2 * x2 * x2;
                float wv = (pbx[base + 4] - q.gth) + HPI_F;
                wv -= PI_F * floorf(wv * IPI_F);
                float wr = fabsf(wv - HPI_F);
                float c = (dxa * dxa + dya * dya) * q.inv_sc2;
                float sg = 1.f / (1.f + __expf(-ps[base + q.lbl]));
                sg = fminf(fmaxf(sg, EPSF), 1.f);
                float lcl = 0.5f * __logf(sg + EPSF);
                float v = fmaxf(q.factor * x6 * __expf(lcl - 1.5f * wr - c), 0.f);
                int slot = atomicAdd(&s_np, 1);
                s_pn[slot] = n; s_pv[slot] = v;
                u64 bk = ((u64)__float_as_uint(v) << 32) | (unsigned)(127 - g);
                atomicMax((u64*)(d_best + b * NN + n), bk);
            }
            __syncthreads();
        }
    }
    __syncthreads();
    int np = s_np;

    // -------- streaming pass: per-column (per-thread) top-2 --------
    u64 t1 = 0, t2 = 0;
    for (int i = tid; i < NQ4; i += 256) {
        float4 v = am4[i];
        if (fb) {
            for (int p = 0; p < np; p++) {
                int pn = s_pn[p];
                if ((pn >> 2) == i) ((float*)&v)[pn & 3] = s_pv[p];
            }
        }
        int n0 = 4 * i;
#pragma unroll
        for (int j = 0; j < 4; j++) {
            float f = (j == 0) ? v.x : (j == 1) ? v.y : (j == 2) ? v.z : v.w;
            u64 k = ((u64)__float_as_uint(f) << 32) | (unsigned)(16384 - (n0 + j));
            if (k > t1)      { t2 = t1; t1 = k; }
            else if (k > t2) { t2 = k; }
        }
    }
    s_k1[tid] = t1;
    s_k2[tid] = t2;
    __syncthreads();
    if (wid != 0) return;

    // -------- warp-0-only 18-round extraction --------
    u64 myk[8];
#pragma unroll
    for (int j2 = 0; j2 < 8; j2++) myk[j2] = s_k1[lane * 8 + j2];
    u64 topkey = 0;

    for (int r = 0; r < MAXTK; r++) {
        u64 m = myk[0];
#pragma unroll
        for (int j2 = 1; j2 < 8; j2++) if (myk[j2] > m) m = myk[j2];
        unsigned hi = (unsigned)(m >> 32);
        unsigned hmax = __reduce_max_sync(0xffffffffu, hi);
        unsigned lo = (hi == hmax) ? (unsigned)m : 0u;
        unsigned lmax = __reduce_max_sync(0xffffffffu, lo);
        if (lane == r) topkey = ((u64)hmax << 32) | lmax;

        int bn = 16384 - (int)lmax;
        int bi = bn >> 2;
        int c  = bi & 255;
        int mi = ((bi >> 8) << 2) | (bn & 3);
        int cnt = 0;
        if (lane == 0) {
            s_rm[c] |= (1ull << mi);
            cnt = s_ecnt[c];
            s_ecnt[c] = (unsigned char)(cnt + 1);
        }
        cnt = __shfl_sync(0xffffffffu, cnt, 0);
        u64 newmax;
        if (cnt == 0) {
            newmax = s_k2[c];                    // precomputed 2nd best
        } else {
            __syncwarp();                        // s_rm[c] visible to all lanes
            u64 rmm = s_rm[c];
            int nv = (c < (NQ4 & 255)) ? 36 : 32;
            u64 nk = 0;
            {
                int mm = lane;
                if (!((rmm >> mm) & 1ull)) {
                    int n2 = 4 * (c + (mm >> 2) * 256) + (mm & 3);
                    float vv = amrow[n2];
                    if (fb) for (int p = 0; p < np; p++) if (s_pn[p] == n2) vv = s_pv[p];
                    nk = ((u64)__float_as_uint(vv) << 32) | (unsigned)(16384 - n2);
                }
                if (nv == 36 && lane < 4) {
                    int mm2 = 32 + lane;
                    if (!((rmm >> mm2) & 1ull)) {
                        int n2 = 4 * (c + (mm2 >> 2) * 256) + (mm2 & 3);
                        float vv = amrow[n2];
                        if (fb) for (int p = 0; p < np; p++) if (s_pn[p] == n2) vv = s_pv[p];
                        u64 k2 = ((u64)__float_as_uint(vv) << 32) | (unsigned)(16384 - n2);
                        if (k2 > nk) nk = k2;
                    }
                }
            }
            unsigned h2 = (unsigned)(nk >> 32);
            unsigned hm2 = __reduce_max_sync(0xffffffffu, h2);
            unsigned lo2 = (h2 == hm2) ? (unsigned)nk : 0u;
            unsigned lm2 = __reduce_max_sync(0xffffffffu, lo2);
            newmax = ((u64)hm2 << 32) | lm2;
        }
        if (lane == (c >> 3)) {
            switch (c & 7) {
                case 0: myk[0] = newmax; break;
                case 1: myk[1] = newmax; break;
                case 2: myk[2] = newmax; break;
                case 3: myk[3] = newmax; break;
                case 4: myk[4] = newmax; break;
                case 5: myk[5] = newmax; break;
                case 6: myk[6] = newmax; break;
                case 7: myk[7] = newmax; break;
            }
        }
    }

    // -------- epilogue (warp 0) --------
    {
        float val = 0.f; unsigned nj = 0; float ovj = 0.f;
        if (lane < MAXTK) {
            val = __uint_as_float((unsigned)(topkey >> 32));
            nj = 16384u - (unsigned)(topkey & 0xffffffffull);
            size_t base = (size_t)(b * NN + nj) * 5;
            float dx = pbx[base] - q.gx, dy = pbx[base + 1] - q.gy;
            float t = (dx * dx + dy * dy) * q.inv_s2;
            ovj = fminf(fmaxf(__expf(-t), 0.f), 1.f);
        }
        float s = ovj;
#pragma unroll
        for (int o = 16; o; o >>= 1) s += __shfl_xor_sync(0xffffffffu, s, o);
        float dk = rintf(s);
        dk = fmaxf(dk, 1.f);
        dk = fminf(dk, (float)q.budget);
        int dyn = (int)dk;
        bool sel = (lane < MAXTK) && (val > EPSF) && (lane < dyn);
        unsigned bal = __ballot_sync(0xffffffffu, sel);
        if (bal) {
            int first = __ffs(bal) - 1;
            float maxalign = __shfl_sync(0xffffffffu, val, first);
            float mo = sel ? ovj : 0.f;
#pragma unroll
            for (int o = 16; o; o >>= 1) mo = fmaxf(mo, __shfl_xor_sync(0xffffffffu, mo, o));
            if (sel) {
                float nv2 = val * mo / (maxalign + EPSF);
                atomicMax(d_norm + b * NN + nj, __float_as_int(nv2));
                d_pos[b * NN + nj] = 1;
            }
        }
    }
}

// ---------------------------------------------------------------------------
__global__ __launch_bounds__(256) void out_kernel(const int* __restrict__ gl,
                                                  const float* __restrict__ gb,
                                                  float* __restrict__ out) {
    int idx = blockIdx.x * 256 + threadIdx.x;
    if (idx >= BN) return;
    int b = idx / NN;
    u64 key = d_best[idx];
    int g = 127 - (int)(key & 0xffffffffull);
    bool pos = d_pos[idx] != 0;
    int lab = gl[b * GG + g];
    out[idx] = pos ? (float)lab : 5.f;
    const float* gp = gb + (size_t)(b * GG + g) * 5;
    float* ob = out + BN + (size_t)idx * 5;
    ob[0] = gp[0]; ob[1] = gp[1]; ob[2] = gp[2]; ob[3] = gp[3]; ob[4] = gp[4];
    float nv = __int_as_float(d_norm[idx]);
    float* os = out + (size_t)BN * 6 + (size_t)idx * 5;
#pragma unroll
    for (int c = 0; c < 5; c++) os[c] = (pos && c == lab) ? nv : 0.f;
    out[(size_t)BN * 11 + idx] = pos ? 1.f : 0.f;
}

// ---------------------------------------------------------------------------
extern "C" void kernel_launch(void* const* d_in, const int* in_sizes, int n_in,
                              void* d_out, int out_size) {
    const float* ps  = (const float*)d_in[0];
    const float* pbx = (const float*)d_in[1];
    const float* ap  = (const float*)d_in[2];
    const int*   gl  = (const int*)d_in[3];
    const float* gbx = (const float*)d_in[4];
    const float* mg  = (const float*)d_in[5];

    prep_gt<<<(BGT + 255) / 256, 256>>>(gl, gbx, mg);
    dim3 ga((NN + 511) / 512, BB);
    pair_kernel<<<ga, 512>>>((const float2*)ap, ps, pbx);
    topk_kernel<<<BGT, 256>>>((const float2*)ap, ps, pbx);
    out_kernel<<<(BN + 255) / 256, 256>>>(gl, gbx, (float*)d_out);
}

// round 11
// speedup vs baseline: 1.2289x; 1.2289x over previous
#include <cuda_runtime.h>
#include <math.h>

#define BB 16
#define NN 8400
#define GG 128
#define NCL 5
#define BN (BB*NN)      // 134400
#define BGT (BB*GG)     // 2048
#define NQ4 (NN/4)      // 2100 float4s per row
#define MAXTK 18
#define EPSF 1e-9f
#define HPI_F 1.57079632679489662f
#define PI_F  3.14159265358979323f
#define IPI_F 0.318309886183790672f

typedef unsigned long long u64;

struct GTC {
    float gx, gy, ct, st;
    float w15, h15, inv_s2, inv_sc2;
    float factor, gth;
    int budget, fbk, flags, lbl;
    float pad0, pad1;
};

__device__ GTC           d_gt[BGT];
__device__ float         d_am[(size_t)BGT * NN];  // [b][g][n]
__device__ u64           d_best[BN];              // (val<<32)|(127-g)
__device__ int           d_norm[BN];
__device__ unsigned char d_pos[BN];
__device__ int           d_cnt[BGT];              // nonzero in-center flag

// ---------------------------------------------------------------------------
__global__ __launch_bounds__(256) void prep_gt(const int* __restrict__ gl,
                                               const float* __restrict__ gb,
                                               const float* __restrict__ mg) {
    int bg = blockIdx.x * 256 + threadIdx.x;
    if (bg >= BGT) return;
    const float* g = gb + (size_t)bg * 5;
    float gx = g[0], gy = g[1], w = g[2], h = g[3], th = g[4];
    float wc = fmaxf(w, EPSF), hc = fmaxf(h, EPSF);
    float area = wc * hc;
    float ar = fmaxf(wc / hc, hc / wc);
    float sev = fminf(fmaxf((0.01f - area) / (0.01f + EPSF), 0.f), 1.f);
    int te = (int)ceilf(sev * 4.f);
    int el = (ar >= 4.f) ? 1 : 0;
    GTC q;
    q.gx = gx; q.gy = gy;
    q.ct = cosf(-th); q.st = sinf(-th);
    q.w15 = w * 1.5f; q.h15 = h * 1.5f;
    float sc = sqrtf(w * h);
    float is = 1.f / (sc + 1e-6f);         q.inv_s2  = is * is;
    float isc = 1.f / (sc * 1.5f + 1e-6f); q.inv_sc2 = isc * isc;
    float strength = fminf(fmaxf((ar - 4.f) / (4.f + EPSF), 0.f), 1.f);
    q.factor = (1.f + sev * (4.f / 13.f)) * (1.f + 0.25f * strength);
    q.gth = th;
    q.budget = 13 + te + el;
    q.fbk = te + el + 3;
    int fl = (mg[bg] > 0.f) ? 1 : 0;
    if ((area < 0.01f) || (ar >= 4.f)) fl |= 2;
    q.flags = fl;
    q.lbl = gl[bg];
    if (!(fl & 1)) q.factor = 0.f;   // masked GT: body yields exactly 0
    q.pad0 = 0.f; q.pad1 = 0.f;
    d_gt[bg] = q;
    d_cnt[bg] = 0;
}

// ---------------------------------------------------------------------------
// A: block = (512-anchor tile, b), 512 threads, 1 anchor/thread, 32 warps/SM.
// Straight-line g-loop (no flags-continue, no ballot) -> pipelineable LDS.
// ---------------------------------------------------------------------------
__global__ __launch_bounds__(512) void pair_kernel(const float2* __restrict__ anch,
                                                   const float* __restrict__ ps,
                                                   const float* __restrict__ pbx) {
    int b   = blockIdx.y;
    int tid = threadIdx.x;
    int n   = blockIdx.x * 512 + tid;

    __shared__ GTC           s_gt[GG];     // 8 KB
    __shared__ unsigned char s_any[GG];

    {
        const float4* src = (const float4*)(d_gt + b * GG);
        float4*       dst = (float4*)s_gt;
        dst[tid] = src[tid];
        if (tid < GG) s_any[tid] = 0;
    }
    __syncthreads();

    bool valid = (n < NN);
    float ax = 0.f, ay = 0.f, px = 0.f, py = 0.f, pt = 0.f;
    float l0 = 0.f, l1 = 0.f, l2 = 0.f, l3 = 0.f, l4 = 0.f;
    if (valid) {
        float2 a = anch[n];
        ax = a.x; ay = a.y;
        size_t base = (size_t)(b * NN + n) * 5;
        px = pbx[base]; py = pbx[base + 1]; pt = pbx[base + 4];
#define LC(d, i) { float sg = 1.f/(1.f+__expf(-ps[base+(i)])); \
                   sg = fminf(fmaxf(sg, EPSF), 1.f); d = 0.5f*__logf(sg+EPSF); }
        LC(l0,0) LC(l1,1) LC(l2,2) LC(l3,3) LC(l4,4)
#undef LC
    }

    float bv = 0.f;
    int   bgi = 0;
    float* amp = d_am + (size_t)b * GG * NN + n;

#pragma unroll 2
    for (int g = 0; g < GG; g++) {
        GTC q = s_gt[g];
        float dxa = ax - q.gx, dya = ay - q.gy;
        float lx = dxa * q.ct - dya * q.st;
        float ly = dxa * q.st + dya * q.ct;
        bool in = valid && (fabsf(lx) < q.w15) && (fabsf(ly) < q.h15);

        float dxp = px - q.gx, dyp = py - q.gy;
        float t = (dxp * dxp + dyp * dyp) * q.inv_s2;
        float x = __expf(-t) + EPSF;
        float x2 = x * x; float x6 = x2 * x2 * x2;
        float wv = (pt - q.gth) + HPI_F;
        wv -= PI_F * floorf(wv * IPI_F);
        float wr = fabsf(wv - HPI_F);
        float c = (dxa * dxa + dya * dya) * q.inv_sc2;
        int lb = q.lbl;
        float lcl = lb == 0 ? l0 : (lb == 1 ? l1 : (lb == 2 ? l2 : (lb == 3 ? l3 : l4)));
        float val = fmaxf(q.factor * x6 * __expf(lcl - 1.5f * wr - c), 0.f);
        float vv = in ? val : 0.f;

        if (in) s_any[g] = 1;
        if (valid) amp[(size_t)g * NN] = vv;
        if (vv > bv) { bv = vv; bgi = g; }
    }
    __syncthreads();
    if (tid < GG && s_any[tid]) atomicOr(&d_cnt[b * GG + tid], 1);
    if (valid) {
        int idx = b * NN + n;
        d_best[idx] = ((u64)__float_as_uint(bv) << 32) | (unsigned)(127 - bgi);
        d_norm[idx] = 0;
        d_pos[idx]  = 0;
    }
}

// ---------------------------------------------------------------------------
// B (R5/R8): block per (b,g). Copy row + column maxima in one pass, then
// warp-0-only 18-round extraction. Column c holds i = c + k*256, n = 4i+j.
// ---------------------------------------------------------------------------
__global__ __launch_bounds__(256) void topk_kernel(const float2* __restrict__ anch,
                                                   const float* __restrict__ ps,
                                                   const float* __restrict__ pbx) {
    int bg = blockIdx.x;
    int b  = bg >> 7;
    GTC q = d_gt[bg];
    if (!(q.flags & 1)) return;

    int tid = threadIdx.x, lane = tid & 31, wid = tid >> 5;

    __shared__ float    s_av[NN];          // 33.6 KB
    __shared__ u64      s_cmax[256];
    __shared__ u64      s_rm[256];
    __shared__ u64      s_red[8];
    __shared__ unsigned s_chosen[8];

    const float4* am4 = (const float4*)(d_am + (size_t)bg * NN);
    float4*       av4 = (float4*)s_av;
    bool fb = (d_cnt[bg] == 0) && (q.flags & 2);

    u64 cm = 0;
    for (int i = tid; i < NQ4; i += 256) {
        float4 v = am4[i];
        av4[i] = v;
        float m4 = fmaxf(fmaxf(v.x, v.y), fmaxf(v.z, v.w));
        int j = (v.x == m4) ? 0 : ((v.y == m4) ? 1 : ((v.z == m4) ? 2 : 3));
        u64 key = ((u64)__float_as_uint(m4) << 32) | (unsigned)(16384 - (4 * i + j));
        if (key > cm) cm = key;
    }
    s_rm[tid] = 0;

    // -------- tiny/elongated fallback (rare) --------
    if (fb) {
        __syncthreads();
        for (int r = 0; r < 8; r++) {
            u64 key = 0xFFFFFFFFFFFFFFFFull;
            for (int n = tid; n < NN; n += 256) {
                bool skip = false;
                for (int qq = 0; qq < r; qq++)
                    if (s_chosen[qq] == (unsigned)n) skip = true;
                if (!skip) {
                    float2 a = anch[n];
                    float dx = a.x - q.gx, dy = a.y - q.gy;
                    float d2 = dx * dx + dy * dy;
                    u64 k = ((u64)__float_as_uint(d2) << 32) | (unsigned)n;
                    if (k < key) key = k;
                }
            }
#pragma unroll
            for (int o = 16; o; o >>= 1) {
                u64 t = __shfl_xor_sync(0xffffffffu, key, o);
                if (t < key) key = t;
            }
            if (lane == 0) s_red[wid] = key;
            __syncthreads();
            if (wid == 0) {
                u64 v = (lane < 8) ? s_red[lane] : 0xFFFFFFFFFFFFFFFFull;
#pragma unroll
                for (int o = 4; o; o >>= 1) {
                    u64 t = __shfl_xor_sync(0xffffffffu, v, o);
                    if (t < v) v = t;
                }
                if (lane == 0) s_chosen[r] = (unsigned)(v & 0xffffffffu);
            }
            __syncthreads();
            unsigned nw = s_chosen[r];
            if (r < q.fbk && (int)(nw & 255u) == tid) {
                int n = (int)nw;
                float2 a = anch[n];
                float dxa = a.x - q.gx, dya = a.y - q.gy;
                size_t base = (size_t)(b * NN + n) * 5;
                float dxp = pbx[base] - q.gx, dyp = pbx[base + 1] - q.gy;
                float t = (dxp * dxp + dyp * dyp) * q.inv_s2;
                float x = __expf(-t) + EPSF;
                float x2 = x * x; float x6 = x2 * x2 * x2;
                float wv = (pbx[base + 4] - q.gth) + HPI_F;
                wv -= PI_F * floorf(wv * IPI_F);
                float wr = fabsf(wv - HPI_F);
                float c = (dxa * dxa + dya * dya) * q.inv_sc2;
                float sg = 1.f / (1.f + __expf(-ps[base + q.lbl]));
                sg = fminf(fmaxf(sg, EPSF), 1.f);
                float lcl = 0.5f * __logf(sg + EPSF);
                float v = fmaxf(q.factor * x6 * __expf(lcl - 1.5f * wr - c), 0.f);
                s_av[n] = v;
                u64 bk = ((u64)__float_as_uint(v) << 32) | (unsigned)(127 - (bg & 127));
                atomicMax((u64*)(d_best + b * NN + n), bk);
            }
            __syncthreads();
        }
        // recompute column maxima after patches
        cm = 0;
        for (int i = tid; i < NQ4; i += 256) {
            float4 v = av4[i];
            float m4 = fmaxf(fmaxf(v.x, v.y), fmaxf(v.z, v.w));
            int j = (v.x == m4) ? 0 : ((v.y == m4) ? 1 : ((v.z == m4) ? 2 : 3));
            u64 key = ((u64)__float_as_uint(m4) << 32) | (unsigned)(16384 - (4 * i + j));
            if (key > cm) cm = key;
        }
    }

    s_cmax[tid] = cm;
    __syncthreads();
    if (wid != 0) return;

    // -------- warp-0-only 18-round extraction --------
    u64 myk[8];
#pragma unroll
    for (int j2 = 0; j2 < 8; j2++) myk[j2] = s_cmax[lane * 8 + j2];
    u64 topkey = 0;

    for (int r = 0; r < MAXTK; r++) {
        u64 m = myk[0];
#pragma unroll
        for (int j2 = 1; j2 < 8; j2++) if (myk[j2] > m) m = myk[j2];
        unsigned hi = (unsigned)(m >> 32);
        unsigned hmax = __reduce_max_sync(0xffffffffu, hi);
        unsigned lo = (hi == hmax) ? (unsigned)m : 0u;
        unsigned lmax = __reduce_max_sync(0xffffffffu, lo);
        if (lane == r) topkey = ((u64)hmax << 32) | lmax;

        int bn = 16384 - (int)lmax;
        int bi = bn >> 2;
        int c  = bi & 255;
        int mi = ((bi >> 8) << 2) | (bn & 3);
        if (lane == 0) s_rm[c] |= (1ull << mi);
        __syncwarp();
        u64 rmm = s_rm[c];
        int nv = (c < (NQ4 & 255)) ? 36 : 32;
        u64 nk = 0;
        {
            int mm = lane;
            if (!((rmm >> mm) & 1ull)) {
                int n2 = 4 * (c + (mm >> 2) * 256) + (mm & 3);
                nk = ((u64)__float_as_uint(s_av[n2]) << 32) | (unsigned)(16384 - n2);
            }
            if (nv == 36 && lane < 4) {
                int mm2 = 32 + lane;
                if (!((rmm >> mm2) & 1ull)) {
                    int n2 = 4 * (c + (mm2 >> 2) * 256) + (mm2 & 3);
                    u64 k2 = ((u64)__float_as_uint(s_av[n2]) << 32) | (unsigned)(16384 - n2);
                    if (k2 > nk) nk = k2;
                }
            }
        }
        unsigned h2 = (unsigned)(nk >> 32);
        unsigned hm2 = __reduce_max_sync(0xffffffffu, h2);
        unsigned lo2 = (h2 == hm2) ? (unsigned)nk : 0u;
        unsigned lm2 = __reduce_max_sync(0xffffffffu, lo2);
        u64 newmax = ((u64)hm2 << 32) | lm2;
        if (lane == (c >> 3)) {
            switch (c & 7) {
                case 0: myk[0] = newmax; break;
                case 1: myk[1] = newmax; break;
                case 2: myk[2] = newmax; break;
                case 3: myk[3] = newmax; break;
                case 4: myk[4] = newmax; break;
                case 5: myk[5] = newmax; break;
                case 6: myk[6] = newmax; break;
                case 7: myk[7] = newmax; break;
            }
        }
    }

    // -------- epilogue (warp 0) --------
    {
        float val = 0.f; unsigned nj = 0; float ovj = 0.f;
        if (lane < MAXTK) {
            val = __uint_as_float((unsigned)(topkey >> 32));
            nj = 16384u - (unsigned)(topkey & 0xffffffffull);
            size_t base = (size_t)(b * NN + nj) * 5;
            float dx = pbx[base] - q.gx, dy = pbx[base + 1] - q.gy;
            float t = (dx * dx + dy * dy) * q.inv_s2;
            ovj = fminf(fmaxf(__expf(-t), 0.f), 1.f);
        }
        float s = ovj;
#pragma unroll
        for (int o = 16; o; o >>= 1) s += __shfl_xor_sync(0xffffffffu, s, o);
        float dk = rintf(s);
        dk = fmaxf(dk, 1.f);
        dk = fminf(dk, (float)q.budget);
        int dyn = (int)dk;
        bool sel = (lane < MAXTK) && (val > EPSF) && (lane < dyn);
        unsigned bal = __ballot_sync(0xffffffffu, sel);
        if (bal) {
            int first = __ffs(bal) - 1;
            float maxalign = __shfl_sync(0xffffffffu, val, first);
            float mo = sel ? ovj : 0.f;
#pragma unroll
            for (int o = 16; o; o >>= 1) mo = fmaxf(mo, __shfl_xor_sync(0xffffffffu, mo, o));
            if (sel) {
                float nv2 = val * mo / (maxalign + EPSF);
                atomicMax(d_norm + b * NN + nj, __float_as_int(nv2));
                d_pos[b * NN + nj] = 1;
            }
        }
    }
}

// ---------------------------------------------------------------------------
__global__ __launch_bounds__(256) void out_kernel(const int* __restrict__ gl,
                                                  const float* __restrict__ gb,
                                                  float* __restrict__ out) {
    int idx = blockIdx.x * 256 + threadIdx.x;
    if (idx >= BN) return;
    int b = idx / NN;
    u64 key = d_best[idx];
    int g = 127 - (int)(key & 0xffffffffull);
    bool pos = d_pos[idx] != 0;
    int lab = gl[b * GG + g];
    out[idx] = pos ? (float)lab : 5.f;
    const float* gp = gb + (size_t)(b * GG + g) * 5;
    float* ob = out + BN + (size_t)idx * 5;
    ob[0] = gp[0]; ob[1] = gp[1]; ob[2] = gp[2]; ob[3] = gp[3]; ob[4] = gp[4];
    float nv = __int_as_float(d_norm[idx]);
    float* os = out + (size_t)BN * 6 + (size_t)idx * 5;
#pragma unroll
    for (int c = 0; c < 5; c++) os[c] = (pos && c == lab) ? nv : 0.f;
    out[(size_t)BN * 11 + idx] = pos ? 1.f : 0.f;
}

// ---------------------------------------------------------------------------
extern "C" void kernel_launch(void* const* d_in, const int* in_sizes, int n_in,
                              void* d_out, int out_size) {
    const float* ps  = (const float*)d_in[0];
    const float* pbx = (const float*)d_in[1];
    const float* ap  = (const float*)d_in[2];
    const int*   gl  = (const int*)d_in[3];
    const float* gbx = (const float*)d_in[4];
    const float* mg  = (const float*)d_in[5];

    prep_gt<<<(BGT + 255) / 256, 256>>>(gl, gbx, mg);
    dim3 ga((NN + 511) / 512, BB);
    pair_kernel<<<ga, 512>>>((const float2*)ap, ps, pbx);
    topk_kernel<<<BGT, 256>>>((const float2*)ap, ps, pbx);
    out_kernel<<<(BN + 255) / 256, 256>>>(gl, gbx, (float*)d_out);
}